// round 1
// baseline (speedup 1.0000x reference)
#include <cuda_runtime.h>
#include <math.h>

#define B_  16
#define L_  4096
#define D_  512
#define LP1 (L_ + 1)

// Per-d angular rate: fp[d] = float(100^{-(d - d%2)/D}) + float(pi/2)*(d%2)
// Computed once per launch by a tiny setup kernel (double pow -> correctly
// rounded f32), then L1/L2-resident for the main kernel.
__device__ float g_fp[D_];

__global__ void setup_fp_kernel() {
    int d = threadIdx.x;
    if (d < D_) {
        double t = (double)(d & ~1) / (double)D_;          // exact: k/256
        float freq = (float)pow(100.0, -t);                // HORIZON = 100
        float phase = (d & 1) ? 1.57079637050628662109375f // float(pi/2)
                              : 0.0f;
        g_fp[d] = freq + phase;                             // f32 add, matches ref
    }
}

// Accurate sin of the f32 angle l*fp (angle formed in f32 exactly like the
// reference), with double-precision Cody-Waite reduction so correctness is
// independent of -use_fast_math (naked sinf would become __sinf and blow up
// at |x| ~ 1e4).
__device__ __forceinline__ float emb_sin(float lf, float fp) {
    float x = __fmul_rn(lf, fp);                 // matches ref's f32 product
    double xd = (double)x;
    double k  = rint(xd * 0.15915494309189533576888376337251);  // 1/(2*pi)
    double r  = fma(-k, 6.283185307179586476925286766559, xd);  // |r| <= pi
    return sinf((float)r);                        // small-arg: cheap & exact
}

__global__ __launch_bounds__(512)
void pe_kernel(const float* __restrict__ tokens,
               const int*   __restrict__ lengths,
               const float* __restrict__ cls,
               float*       __restrict__ out) {
    // One row per warp-group-of-4-warps: 128 threads cover D=512 via float4.
    // blockDim = (128, 4) -> 4 rows per block. Rows 0..L inclusive (L+1 rows).
    int row = blockIdx.x * 4 + threadIdx.y;
    if (row > L_) return;

    int d4 = threadIdx.x;                 // float4 index within the row
    int dd = d4 * 4;

    float4 fp   = *reinterpret_cast<const float4*>(g_fp + dd);
    float4 cls4 = *reinterpret_cast<const float4*>(cls  + dd);

    // Positional embedding for this (row, d..d+3) — computed ONCE, reused
    // across all 16 batch elements. Row L has no embedding.
    float4 emb = make_float4(0.f, 0.f, 0.f, 0.f);
    if (row < L_) {
        float lf = (float)row;
        emb.x = emb_sin(lf, fp.x);
        emb.y = emb_sin(lf, fp.y);
        emb.z = emb_sin(lf, fp.z);
        emb.w = emb_sin(lf, fp.w);
    }

    int lens[B_];
#pragma unroll
    for (int b = 0; b < B_; b++) lens[b] = __ldg(lengths + b);

#pragma unroll
    for (int b = 0; b < B_; b++) {
        float4 o;
        if (row < lens[b]) {
            // valid token: tokens + emb
            const float4 t = *reinterpret_cast<const float4*>(
                tokens + ((size_t)b * L_ + row) * D_ + dd);
            o = make_float4(t.x + emb.x, t.y + emb.y, t.z + emb.z, t.w + emb.w);
        } else if (row == lens[b]) {
            // CLS row (x was zeroed here in the reference, so out = cls)
            o = cls4;
        } else {
            o = make_float4(0.f, 0.f, 0.f, 0.f);
        }
        *reinterpret_cast<float4*>(
            out + ((size_t)b * LP1 + row) * D_ + dd) = o;
    }
}

extern "C" void kernel_launch(void* const* d_in, const int* in_sizes, int n_in,
                              void* d_out, int out_size) {
    const float* tokens  = (const float*)d_in[0];  // [B, L, D] f32
    const int*   lengths = (const int*)  d_in[1];  // [B] i32
    const float* cls     = (const float*)d_in[2];  // [D] f32
    float*       out     = (float*)d_out;          // [B, L+1, D] f32

    (void)in_sizes; (void)n_in; (void)out_size;

    setup_fp_kernel<<<1, 512>>>();

    dim3 blk(128, 4);
    int grid = (LP1 + 3) / 4;                      // 1025 blocks, rows 0..4096
    pe_kernel<<<grid, blk>>>(tokens, lengths, cls, out);
}

// round 2
// speedup vs baseline: 1.1725x; 1.1725x over previous
#include <cuda_runtime.h>
#include <math.h>

#define B_  16
#define L_  4096
#define D_  512
#define LP1 (L_ + 1)

// sin of the f32 angle l*fp (angle formed in f32 exactly like the reference),
// with double-precision Cody-Waite reduction so correctness is independent of
// --use_fast_math (naked sinf would become __sinf and blow up at |x| ~ 1e4).
__device__ __forceinline__ float emb_sin(float lf, float fp) {
    float x = __fmul_rn(lf, fp);                 // matches ref's f32 product
    double xd = (double)x;
    double k  = rint(xd * 0.15915494309189533576888376337251);  // 1/(2*pi)
    double r  = fma(-k, 6.283185307179586476925286766559, xd);  // |r| <= pi
    return sinf((float)r);                        // small-arg: cheap & exact
}

__global__ __launch_bounds__(512, 2)
void pe_kernel(const float* __restrict__ tokens,
               const int*   __restrict__ lengths,
               const float* __restrict__ cls,
               float*       __restrict__ out) {
    // blockDim = (128, 4): 4 rows per block, 128 threads x float4 cover D=512.
    __shared__ float s_fp[D_];
    __shared__ int   s_len[B_];

    int d4 = threadIdx.x;                 // float4 index within the row
    int dd = d4 * 4;
    int lin = threadIdx.y * 128 + threadIdx.x;

    // --- per-block setup: fp table (double exp -> f32, == correctly rounded
    //     100^-t) and lengths into smem. 256 exps/block, amortized. ---
    if (threadIdx.y == 0) {
        const double LN100 = 4.605170185988091368;
        const float  PI2F  = 1.57079637050628662109375f;  // float(pi/2)
        double t0 = (double)dd       / (double)D_;
        double t1 = (double)(dd + 2) / (double)D_;
        float f0 = (float)exp(-t0 * LN100);
        float f1 = (float)exp(-t1 * LN100);
        s_fp[dd + 0] = f0;
        s_fp[dd + 1] = f0 + PI2F;   // f32 add, matches ref
        s_fp[dd + 2] = f1;
        s_fp[dd + 3] = f1 + PI2F;
    }
    if (lin < B_) s_len[lin] = lengths[lin];
    __syncthreads();

    int row = blockIdx.x * 4 + threadIdx.y;
    if (row > L_) return;                 // safe: after the only __syncthreads

    float4 fp   = *reinterpret_cast<const float4*>(s_fp + dd);
    float4 cls4 = *reinterpret_cast<const float4*>(cls  + dd);

    // Positional embedding for this (row, dd..dd+3) — computed ONCE, reused
    // across all 16 batch elements. Row L has no embedding.
    float4 emb = make_float4(0.f, 0.f, 0.f, 0.f);
    if (row < L_) {
        float lf = (float)row;
        emb.x = emb_sin(lf, fp.x);
        emb.y = emb_sin(lf, fp.y);
        emb.z = emb_sin(lf, fp.z);
        emb.w = emb_sin(lf, fp.w);
    }

    const float* tok_row = tokens + (size_t)row * D_ + dd;
    float*       out_row = out    + (size_t)row * D_ + dd;

    // Batch loop staged in groups of 8: 8 independent LDG.128 in flight
    // before the dependent FADD+STG group -> MLP ~8 per thread.
#pragma unroll
    for (int bb = 0; bb < B_; bb += 8) {
        float4 t4[8];
#pragma unroll
        for (int j = 0; j < 8; j++) {
            int b = bb + j;
            if (row < s_len[b])
                t4[j] = *reinterpret_cast<const float4*>(
                            tok_row + (size_t)b * ((size_t)L_ * D_));
        }
#pragma unroll
        for (int j = 0; j < 8; j++) {
            int b   = bb + j;
            int len = s_len[b];
            float4 o;
            if (row < len) {
                o = make_float4(t4[j].x + emb.x, t4[j].y + emb.y,
                                t4[j].z + emb.z, t4[j].w + emb.w);
            } else if (row == len) {
                o = cls4;                 // x was zeroed here, so out = cls
            } else {
                o = make_float4(0.f, 0.f, 0.f, 0.f);
            }
            *reinterpret_cast<float4*>(
                out_row + (size_t)b * ((size_t)LP1 * D_)) = o;
        }
    }
}

extern "C" void kernel_launch(void* const* d_in, const int* in_sizes, int n_in,
                              void* d_out, int out_size) {
    const float* tokens  = (const float*)d_in[0];  // [B, L, D] f32
    const int*   lengths = (const int*)  d_in[1];  // [B] i32
    const float* cls     = (const float*)d_in[2];  // [D] f32
    float*       out     = (float*)d_out;          // [B, L+1, D] f32

    (void)in_sizes; (void)n_in; (void)out_size;

    dim3 blk(128, 4);
    int grid = (LP1 + 3) / 4;                      // 1025 blocks, rows 0..4096
    pe_kernel<<<grid, blk>>>(tokens, lengths, cls, out);
}

// round 3
// speedup vs baseline: 1.1799x; 1.0063x over previous
#include <cuda_runtime.h>
#include <math.h>

#define B_  16
#define L_  4096
#define D_  512
#define LP1 (L_ + 1)

// b = 100^(-1/256) = exp(-ln(100)/256), correctly rounded double.
#define POW_BASE 0.9821718891880367

// sin of the f32 angle l*fp (angle formed in f32 exactly like the reference),
// with double-precision Cody-Waite reduction so correctness is independent of
// --use_fast_math (naked sinf would become __sinf and blow up at |x| ~ 1e4).
__device__ __forceinline__ float emb_sin(float lf, float fp) {
    float x = __fmul_rn(lf, fp);                 // matches ref's f32 product
    double xd = (double)x;
    double k  = rint(xd * 0.15915494309189533576888376337251);  // 1/(2*pi)
    double r  = fma(-k, 6.283185307179586476925286766559, xd);  // |r| <= pi
    return sinf((float)r);                        // small-arg: cheap & exact
}

__global__ __launch_bounds__(512, 3)
void pe_kernel(const float* __restrict__ tokens,
               const int*   __restrict__ lengths,
               const float* __restrict__ cls,
               float*       __restrict__ out) {
    // blockDim = (128, 4): 4 rows per block, 128 threads x float4 cover D=512.
    __shared__ int s_len[B_];

    int d4 = threadIdx.x;                 // float4 index within the row
    int dd = d4 * 4;
    int lin = threadIdx.y * 128 + threadIdx.x;

    if (lin < B_) s_len[lin] = lengths[lin];
    __syncthreads();

    int row = blockIdx.x * 4 + threadIdx.y;
    if (row > L_) return;                 // after the only __syncthreads

    const float* tok_row = tokens + (size_t)row * D_ + dd;
    float*       out_row = out    + (size_t)row * D_ + dd;

    // Per-thread freqs via pow-by-squaring in double (no exp, no smem table):
    //   f0 = b^(2*d4), f1 = b^(2*d4+1),  b = 100^(-1/256)
    // => fp = {f0, f0+pi/2, f1, f1+pi/2} matching the reference bit-for-bit
    //    after f32 rounding.
    double p  = 1.0;
    double bs = POW_BASE * POW_BASE;      // b^2
    int k = d4;                            // 7 bits
#pragma unroll
    for (int i = 0; i < 7; i++) {
        if (k & 1) p *= bs;
        bs *= bs;
        k >>= 1;
    }
    const float PI2F = 1.57079637050628662109375f;  // float(pi/2)
    float f0 = (float)p;
    float f1 = (float)(p * POW_BASE);
    float4 fp = make_float4(f0, f0 + PI2F, f1, f1 + PI2F);

    float4 cls4 = *reinterpret_cast<const float4*>(cls + dd);

    // Positional embedding for this (row, dd..dd+3) — computed ONCE, reused
    // across all 16 batch elements. Row L has no embedding.
    float4 emb = make_float4(0.f, 0.f, 0.f, 0.f);
    if (row < L_) {
        float lf = (float)row;
        emb.x = emb_sin(lf, fp.x);
        emb.y = emb_sin(lf, fp.y);
        emb.z = emb_sin(lf, fp.z);
        emb.w = emb_sin(lf, fp.w);
    }

    // Batch loop staged in groups of 4: 4 independent LDG.128 in flight
    // before the dependent FADD+STG group. Occupancy-friendly (<=42 regs).
#pragma unroll
    for (int bb = 0; bb < B_; bb += 4) {
        float4 t4[4];
#pragma unroll
        for (int j = 0; j < 4; j++) {
            int b = bb + j;
            if (row < s_len[b])
                t4[j] = *reinterpret_cast<const float4*>(
                            tok_row + (size_t)b * ((size_t)L_ * D_));
        }
#pragma unroll
        for (int j = 0; j < 4; j++) {
            int b   = bb + j;
            int len = s_len[b];
            float4 o;
            if (row < len) {
                o = make_float4(t4[j].x + emb.x, t4[j].y + emb.y,
                                t4[j].z + emb.z, t4[j].w + emb.w);
            } else if (row == len) {
                o = cls4;                 // x was zeroed here, so out = cls
            } else {
                o = make_float4(0.f, 0.f, 0.f, 0.f);
            }
            *reinterpret_cast<float4*>(
                out_row + (size_t)b * ((size_t)LP1 * D_)) = o;
        }
    }
}

extern "C" void kernel_launch(void* const* d_in, const int* in_sizes, int n_in,
                              void* d_out, int out_size) {
    const float* tokens  = (const float*)d_in[0];  // [B, L, D] f32
    const int*   lengths = (const int*)  d_in[1];  // [B] i32
    const float* cls     = (const float*)d_in[2];  // [D] f32
    float*       out     = (float*)d_out;          // [B, L+1, D] f32

    (void)in_sizes; (void)n_in; (void)out_size;

    dim3 blk(128, 4);
    int grid = (LP1 + 3) / 4;                      // 1025 blocks, rows 0..4096
    pe_kernel<<<grid, blk>>>(tokens, lengths, cls, out);
}